// round 3
// baseline (speedup 1.0000x reference)
#include <cuda_runtime.h>
#include <cuda_bf16.h>

#define CDIM 10000
#define CV4  2500
#define BDIM 4096
#define NT   256
#define NW   8
#define CAP  2048

// dynamic smem layout (bytes):
//   s_key : 10000 u32  = 40000
//   s_hist: 2048  u32  =  8192   (per-warp hist 8x256 -> suffix scan -> cand keys)
//   s_red : 16    f32  =     64
#define SMEM_BYTES (40000 + 8192 + 64)

__device__ float g_partial[BDIM];

__device__ __forceinline__ unsigned key_of(float f) {
    unsigned u = __float_as_uint(f);
    return u ^ ((unsigned)((int)u >> 31) | 0x80000000u);
}
__device__ __forceinline__ float val_of(unsigned k) {
    unsigned m = ((int)k < 0) ? 0x80000000u : 0xFFFFFFFFu;
    return __uint_as_float(k ^ m);
}

// exp(x) for x <= 0, pure FFMA (no MUFU). rel err ~2e-7.
__device__ __forceinline__ float fexp_(float x) {
    x = fmaxf(x, -87.0f);
    const float LOG2E = 1.4426950408889634f;
    float t = fmaf(x, LOG2E, 12582912.0f);       // 1.5*2^23 rounding magic
    unsigned ei = __float_as_uint(t);
    float r = t - 12582912.0f;                   // = round(x*log2e)
    float f = fmaf(x, LOG2E, -r);                // f in [-0.5, 0.5]
    float p = 1.3333558146e-3f;
    p = fmaf(p, f, 9.6181291076e-3f);
    p = fmaf(p, f, 5.5504108664e-2f);
    p = fmaf(p, f, 2.4022650695910071e-1f);
    p = fmaf(p, f, 6.9314718055994531e-1f);
    p = fmaf(p, f, 1.0f);
    return p * __uint_as_float((ei << 23) + 0x3F800000u);
}

__global__ void __launch_bounds__(NT, 4) row_kernel(
    const float* __restrict__ logit, const int* __restrict__ target,
    const float* __restrict__ lcn,   const int* __restrict__ kpc)
{
    extern __shared__ unsigned char smem_raw[];
    unsigned* s_key  = (unsigned*)smem_raw;            // [10000]
    unsigned* s_hist = s_key + CDIM;                   // [2048]
    float*    s_red  = (float*)(s_hist + CAP);         // [16]

    __shared__ float    s_M, s_Z, s_S;
    __shared__ int      s_k, s_tg, s_b3;
    __shared__ unsigned s_ncand, s_T, s_cnt;

    const int row  = blockIdx.x;
    const int tid  = threadIdx.x;
    const int lane = tid & 31;
    const int wid  = tid >> 5;

    // early: fetch target + k (dependent gmem loads, overlapped with pass 1)
    if (tid == NT - 1) {
        int tg = target[row];
        int k = kpc[tg];
        if (k > CDIM) k = CDIM;
        if (k < 1) k = 1;
        s_tg = tg; s_k = k;
    }
    // zero per-warp hist
    for (int i = tid; i < NW * 256; i += NT) s_hist[i] = 0u;
    // NOTE: hist atomics below only touch this warp's own 256-bin slice, and
    // each warp zeroes a disjoint contiguous chunk == its own? No: chunks are
    // strided. So we need a barrier before atomics.
    __syncthreads();

    // ---- pass 1: gmem load, key store, per-warp hist, online softmax ----
    const float4* l4 = (const float4*)(logit + (size_t)row * CDIM);
    const float4* w4 = (const float4*)lcn;
    unsigned* myhist = s_hist + wid * 256;

    float m0 = -3.0e38f, Z0 = 0.f, m1 = -3.0e38f, Z1 = 0.f;
    for (int j4 = tid; j4 < CV4; j4 += NT) {
        float4 L = __ldcs(l4 + j4);
        float4 W = __ldg(w4 + j4);
        uint4 kv;
        kv.x = key_of(L.x); kv.y = key_of(L.y);
        kv.z = key_of(L.z); kv.w = key_of(L.w);
        ((uint4*)s_key)[j4] = kv;
        atomicAdd(&myhist[kv.x >> 24], 1u);
        atomicAdd(&myhist[kv.y >> 24], 1u);
        atomicAdd(&myhist[kv.z >> 24], 1u);
        atomicAdd(&myhist[kv.w >> 24], 1u);
        float a;
        a = L.x + W.x;
        if (a > m0) { Z0 = fmaf(Z0, fexp_(m0 - a), 1.0f); m0 = a; } else Z0 += fexp_(a - m0);
        a = L.y + W.y;
        if (a > m1) { Z1 = fmaf(Z1, fexp_(m1 - a), 1.0f); m1 = a; } else Z1 += fexp_(a - m1);
        a = L.z + W.z;
        if (a > m0) { Z0 = fmaf(Z0, fexp_(m0 - a), 1.0f); m0 = a; } else Z0 += fexp_(a - m0);
        a = L.w + W.w;
        if (a > m1) { Z1 = fmaf(Z1, fexp_(m1 - a), 1.0f); m1 = a; } else Z1 += fexp_(a - m1);
    }
    // merge two chains
    float m = fmaxf(m0, m1);
    float Z = Z0 * fexp_(m0 - m) + Z1 * fexp_(m1 - m);
    // warp reduce (m, Z)
    #pragma unroll
    for (int o = 16; o; o >>= 1) {
        float m2 = __shfl_xor_sync(0xFFFFFFFFu, m, o);
        float Z2 = __shfl_xor_sync(0xFFFFFFFFu, Z, o);
        float mn = fmaxf(m, m2);
        Z = Z * fexp_(m - mn) + Z2 * fexp_(m2 - mn);
        m = mn;
    }
    if (lane == 0) { s_red[wid] = m; s_red[NW + wid] = Z; }
    __syncthreads();   // keys, hist, s_red, s_k all complete

    // ---- column-sum hist + suffix scan (thread b owns bin b) ----
    {
        unsigned tot = 0;
        #pragma unroll
        for (int w = 0; w < NW; w++) tot += s_hist[w * 256 + tid];
        s_hist[tid] = tot;   // only thread b reads/writes column b slot 0
    }
    __syncthreads();
    #pragma unroll
    for (int d = 1; d < 256; d <<= 1) {
        unsigned v = s_hist[tid];
        if (tid + d < 256) v += s_hist[tid + d];
        __syncthreads();
        s_hist[tid] = v;
        __syncthreads();
    }
    {
        int k = s_k;
        unsigned sb = s_hist[tid];
        unsigned snext = (tid < 255) ? s_hist[tid + 1] : 0u;
        if ((int)sb >= k && (tid == 255 || (int)snext < k)) s_b3 = tid;
    }
    if (tid == 0) {
        // merge per-warp (m, Z)
        float M = s_red[0], ZZ = s_red[NW];
        #pragma unroll
        for (int w = 1; w < NW; w++) {
            float m2 = s_red[w], Z2 = s_red[NW + w];
            float mn = fmaxf(M, m2);
            ZZ = ZZ * fexp_(M - mn) + Z2 * fexp_(m2 - mn);
            M = mn;
        }
        s_M = M; s_Z = ZZ;
        s_ncand = 0u; s_cnt = 0u;
    }
    __syncthreads();

    // ---- compact candidates: keys with top byte >= b3 (cnt >= k guaranteed) ----
    const unsigned b3 = (unsigned)s_b3;
    const int k = s_k;
    for (int j = tid; j < 10240; j += NT) {
        bool in = (j < CDIM);
        unsigned kk = in ? s_key[j] : 0u;
        bool sel = in && ((kk >> 24) >= b3);
        unsigned bal = __ballot_sync(0xFFFFFFFFu, sel);
        if (bal) {
            unsigned base = 0;
            if (lane == 0) base = atomicAdd(&s_ncand, (unsigned)__popc(bal));
            base = __shfl_sync(0xFFFFFFFFu, base, 0);
            if (sel) {
                unsigned pos = base + __popc(bal & ((1u << lane) - 1u));
                if (pos < CAP) s_hist[pos] = kk;   // hist region reused as cand keys
            }
        }
    }
    __syncthreads();
    const unsigned n = s_ncand;
    const unsigned base24 = b3 << 24;

    // ---- exact k-th largest: 24-bit bisection ----
    if (n <= CAP) {
        if (wid == 0) {   // warp 0 only, no block barriers
            unsigned lo = 0u, hi = 1u << 24;     // cnt(>=base+lo)>=k, cnt(>=base+hi)<k
            while (hi - lo > 1u) {
                unsigned mid = (lo + hi) >> 1;
                unsigned thr = base24 + mid;
                unsigned c = 0;
                for (unsigned i = lane; i < n; i += 32) c += (s_hist[i] >= thr);
                c = __reduce_add_sync(0xFFFFFFFFu, c);
                if ((int)c >= k) lo = mid; else hi = mid;
            }
            if (lane == 0) s_T = base24 + lo;
        }
    } else {
        // exact fallback: block-wide bisection over full key array
        unsigned lo = 0u, hi = 1u << 24;
        while (hi - lo > 1u) {
            unsigned mid = (lo + hi) >> 1;
            unsigned thr = base24 + mid;
            unsigned c = 0;
            for (int j = tid; j < CDIM; j += NT) c += (s_key[j] >= thr);
            atomicAdd(&s_cnt, c);
            __syncthreads();
            unsigned ct = s_cnt;
            __syncthreads();
            if (tid == 0) s_cnt = 0u;
            if ((int)ct >= k) lo = mid; else hi = mid;
            __syncthreads();
        }
        if (tid == 0) s_T = base24 + lo;
    }
    __syncthreads();
    const unsigned T = s_T;
    const float M = s_M;

    // ---- masked exp-sum over full array (deterministic fixed order) ----
    float s = 0.f;
    for (int j = tid; j < CDIM; j += NT) {
        unsigned kk = s_key[j];
        if (kk >= T) {
            float a = val_of(kk) + __ldg(lcn + j);
            s += fexp_(a - M);
        }
    }
    #pragma unroll
    for (int o = 16; o; o >>= 1) s += __shfl_xor_sync(0xFFFFFFFFu, s, o);
    if (lane == 0) s_red[wid] = s;
    __syncthreads();

    if (tid == 0) {
        float S = 0.f;
        #pragma unroll
        for (int w = 0; w < NW; w++) S += s_red[w];
        float Zt   = s_Z;
        float logZ = logf(Zt);
        int   tg   = s_tg;
        unsigned kt = s_key[tg];
        float at = val_of(kt) + __ldg(lcn + tg);
        float lt = (at - M) - logZ;                   // log_p_adj[target]
        float Sfrac = S / Zt;
        float den = Sfrac + 0.01f;                    // + 1e-6 * C
        float pt  = (kt >= T) ? expf(lt) : 0.f;
        float num = pt + 1e-6f;
        float part = 0.5f * (-lt) + 0.5f * (logf(den) - logf(num));
        g_partial[row] = part;
    }
}

__global__ void reduce_kernel(float* __restrict__ out)
{
    __shared__ float sm[NT];
    int tid = threadIdx.x;
    float s = 0.f;
    for (int i = tid; i < BDIM; i += NT) s += g_partial[i];
    sm[tid] = s;
    __syncthreads();
    #pragma unroll
    for (int o = NT / 2; o; o >>= 1) {
        if (tid < o) sm[tid] += sm[tid + o];
        __syncthreads();
    }
    if (tid == 0) out[0] = sm[0] * (1.0f / BDIM);
}

extern "C" void kernel_launch(void* const* d_in, const int* in_sizes, int n_in,
                              void* d_out, int out_size) {
    const float* logit  = (const float*)d_in[0];
    const int*   target = (const int*)d_in[1];
    const float* lcn    = (const float*)d_in[2];
    const int*   kpc    = (const int*)d_in[3];
    float* out = (float*)d_out;

    cudaFuncSetAttribute(row_kernel, cudaFuncAttributeMaxDynamicSharedMemorySize, SMEM_BYTES);
    row_kernel<<<BDIM, NT, SMEM_BYTES>>>(logit, target, lcn, kpc);
    reduce_kernel<<<1, NT>>>(out);
}

// round 4
// speedup vs baseline: 1.2807x; 1.2807x over previous
#include <cuda_runtime.h>
#include <cuda_bf16.h>

#define CDIM 10000
#define CV4  2500
#define BDIM 4096
#define NT   256
#define NW   8
#define CAP  1024

// dynamic smem: keys 40000B + cand 4096B + red 128B
#define SMEM_BYTES (40000 + 4096 + 128)

__device__ float g_partial[BDIM];

__device__ __forceinline__ unsigned key_of(float f) {
    unsigned u = __float_as_uint(f);
    return u ^ ((unsigned)((int)u >> 31) | 0x80000000u);
}
__device__ __forceinline__ float val_of(unsigned k) {
    unsigned m = ((int)k < 0) ? 0x80000000u : 0xFFFFFFFFu;
    return __uint_as_float(k ^ m);
}

// exp(x), pure FFMA (no MUFU). valid for x <= ~1, rel err ~2e-7.
__device__ __forceinline__ float fexp_(float x) {
    x = fmaxf(x, -87.0f);
    const float LOG2E = 1.4426950408889634f;
    float t = fmaf(x, LOG2E, 12582912.0f);       // 1.5*2^23 rounding magic
    unsigned ei = __float_as_uint(t);
    float f = fmaf(x, LOG2E, -(t - 12582912.0f)); // f in [-0.5, 0.5]
    float p = 1.3333558146e-3f;
    p = fmaf(p, f, 9.6181291076e-3f);
    p = fmaf(p, f, 5.5504108664e-2f);
    p = fmaf(p, f, 2.4022650695910071e-1f);
    p = fmaf(p, f, 6.9314718055994531e-1f);
    p = fmaf(p, f, 1.0f);
    return p * __uint_as_float((ei << 23) + 0x3F800000u);
}

__global__ void __launch_bounds__(NT, 4) row_kernel(
    const float* __restrict__ logit, const int* __restrict__ target,
    const float* __restrict__ lcn,   const int* __restrict__ kpc)
{
    extern __shared__ unsigned char smem_raw[];
    unsigned* s_key  = (unsigned*)smem_raw;            // [10000]
    unsigned* s_cand = s_key + CDIM;                   // [1024]
    float*    s_red  = (float*)(s_cand + CAP);         // [24] floats
    unsigned* s_ru   = (unsigned*)(s_red + 24);        // [8]

    __shared__ float    s_Zs;
    __shared__ int      s_k, s_tg;
    __shared__ unsigned s_T, s_ncand, s_cnt, s_cutkey, s_maxk;

    const int row  = blockIdx.x;
    const int tid  = threadIdx.x;
    const int lane = tid & 31;
    const int wid  = tid >> 5;

    // early fetch of target + k (dependent gmem loads overlap pass 1)
    if (tid == NT - 1) {
        int tg = target[row];
        int k = kpc[tg];
        if (k > CDIM) k = CDIM;
        if (k < 1) k = 1;
        s_tg = tg; s_k = k;
    }

    // ---- pass 1: load, key store, stats, softmax denominator (M = 0) ----
    const float4* l4 = (const float4*)(logit + (size_t)row * CDIM);
    const float4* w4 = (const float4*)lcn;

    float Z0 = 0.f, Z1 = 0.f, s1 = 0.f, s2 = 0.f;
    unsigned maxk = 0u;
    for (int j4 = tid; j4 < CV4; j4 += NT) {
        float4 L = __ldcs(l4 + j4);
        float4 W = __ldg(w4 + j4);
        uint4 kv;
        kv.x = key_of(L.x); kv.y = key_of(L.y);
        kv.z = key_of(L.z); kv.w = key_of(L.w);
        ((uint4*)s_key)[j4] = kv;
        maxk = max(max(max(maxk, kv.x), kv.y), max(kv.z, kv.w));
        s1 += (L.x + L.y) + (L.z + L.w);
        s2 = fmaf(L.x, L.x, s2); s2 = fmaf(L.y, L.y, s2);
        s2 = fmaf(L.z, L.z, s2); s2 = fmaf(L.w, L.w, s2);
        Z0 += fexp_(L.x + W.x);
        Z1 += fexp_(L.y + W.y);
        Z0 += fexp_(L.z + W.z);
        Z1 += fexp_(L.w + W.w);
    }
    float Z = Z0 + Z1;
    #pragma unroll
    for (int o = 16; o; o >>= 1) {
        Z  += __shfl_xor_sync(0xFFFFFFFFu, Z, o);
        s1 += __shfl_xor_sync(0xFFFFFFFFu, s1, o);
        s2 += __shfl_xor_sync(0xFFFFFFFFu, s2, o);
        maxk = max(maxk, __shfl_xor_sync(0xFFFFFFFFu, maxk, o));
    }
    if (lane == 0) {
        s_red[wid] = Z; s_red[NW + wid] = s1; s_red[2 * NW + wid] = s2;
        s_ru[wid] = maxk;
    }
    __syncthreads();

    if (tid == 0) {
        float Zt = 0.f, S1 = 0.f, S2 = 0.f;
        unsigned MK = 0u;
        #pragma unroll
        for (int w = 0; w < NW; w++) {
            Zt += s_red[w]; S1 += s_red[NW + w]; S2 += s_red[2 * NW + w];
            MK = max(MK, s_ru[w]);
        }
        s_Zs = Zt;
        float mu  = S1 * (1.0f / CDIM);
        float var = fmaxf(S2 * (1.0f / CDIM) - mu * mu, 0.0f);
        float cut = mu + 1.75f * sqrtf(var);       // ~top-400 for gaussian rows
        s_cutkey = key_of(cut);
        s_maxk = MK;
        s_ncand = 0u; s_cnt = 0u;
    }
    __syncthreads();

    // ---- compact candidates: keys >= cutkey ----
    const unsigned ck = s_cutkey;
    for (int j = tid; j < 10240; j += NT) {
        bool in = (j < CDIM);
        unsigned kk = in ? s_key[j] : 0u;
        bool sel = in && (kk >= ck);
        unsigned bal = __ballot_sync(0xFFFFFFFFu, sel);
        if (bal) {
            unsigned base = 0;
            if (lane == 0) base = atomicAdd(&s_ncand, (unsigned)__popc(bal));
            base = __shfl_sync(0xFFFFFFFFu, base, 0);
            if (sel) {
                unsigned pos = base + __popc(bal & ((1u << lane) - 1u));
                if (pos < CAP) s_cand[pos] = kk;
            }
        }
    }
    __syncthreads();
    const unsigned n = s_ncand;
    const int k = s_k;

    // ---- exact k-th largest ----
    if ((int)n >= k && n <= CAP) {
        if (wid == 0) {   // warp-0-only bisection over candidates
            unsigned lo = ck, hi = s_maxk + 1u;    // cnt(>=lo)=n>=k, cnt(>=hi)=0<k
            while (hi - lo > 1u) {
                unsigned mid = lo + ((hi - lo) >> 1);
                unsigned c = 0;
                for (unsigned i = lane; i < n; i += 32) c += (s_cand[i] >= mid);
                c = __reduce_add_sync(0xFFFFFFFFu, c);
                if ((int)c >= k) lo = mid; else hi = mid;
            }
            if (lane == 0) s_T = lo;
        }
    } else {
        // exact fallback: block bisection over full key array (rarely taken)
        unsigned lo = 0u, hi = s_maxk + 1u;
        while (hi - lo > 1u) {
            unsigned mid = lo + ((hi - lo) >> 1);
            unsigned c = 0;
            for (int j = tid; j < CDIM; j += NT) c += (s_key[j] >= mid);
            atomicAdd(&s_cnt, c);
            __syncthreads();
            unsigned ct = s_cnt;
            __syncthreads();
            if (tid == 0) s_cnt = 0u;
            if ((int)ct >= k) lo = mid; else hi = mid;
            __syncthreads();
        }
        if (tid == 0) s_T = lo;
    }
    __syncthreads();
    const unsigned T = s_T;

    // ---- masked exp-sum, fixed deterministic order ----
    float s = 0.f;
    for (int j4 = tid; j4 < CV4; j4 += NT) {
        uint4 kv = ((const uint4*)s_key)[j4];
        int j = 4 * j4;
        if (kv.x >= T) s += fexp_(val_of(kv.x) + __ldg(lcn + j));
        if (kv.y >= T) s += fexp_(val_of(kv.y) + __ldg(lcn + j + 1));
        if (kv.z >= T) s += fexp_(val_of(kv.z) + __ldg(lcn + j + 2));
        if (kv.w >= T) s += fexp_(val_of(kv.w) + __ldg(lcn + j + 3));
    }
    #pragma unroll
    for (int o = 16; o; o >>= 1) s += __shfl_xor_sync(0xFFFFFFFFu, s, o);
    if (lane == 0) s_red[wid] = s;
    __syncthreads();

    if (tid == 0) {
        float S = 0.f;
        #pragma unroll
        for (int w = 0; w < NW; w++) S += s_red[w];
        float Zt   = s_Zs;
        float logZ = logf(Zt);
        int   tg   = s_tg;
        unsigned kt = s_key[tg];
        float at = val_of(kt) + __ldg(lcn + tg);
        float pt = (kt >= T) ? (fexp_(at) / Zt) : 0.f;
        float den = S / Zt + 0.01f;                // + 1e-6 * C
        float num = pt + 1e-6f;
        float part = 0.5f * (logZ - at) + 0.5f * (logf(den) - logf(num));
        g_partial[row] = part;
    }
}

__global__ void reduce_kernel(float* __restrict__ out)
{
    __shared__ float sm[1024];
    int tid = threadIdx.x;
    float4 v = ((const float4*)g_partial)[tid];   // 4096 = 1024 * 4
    sm[tid] = (v.x + v.y) + (v.z + v.w);
    __syncthreads();
    #pragma unroll
    for (int o = 512; o; o >>= 1) {
        if (tid < o) sm[tid] += sm[tid + o];
        __syncthreads();
    }
    if (tid == 0) out[0] = sm[0] * (1.0f / BDIM);
}

extern "C" void kernel_launch(void* const* d_in, const int* in_sizes, int n_in,
                              void* d_out, int out_size) {
    const float* logit  = (const float*)d_in[0];
    const int*   target = (const int*)d_in[1];
    const float* lcn    = (const float*)d_in[2];
    const int*   kpc    = (const int*)d_in[3];
    float* out = (float*)d_out;

    row_kernel<<<BDIM, NT, SMEM_BYTES>>>(logit, target, lcn, kpc);
    reduce_kernel<<<1, 1024>>>(out);
}

// round 6
// speedup vs baseline: 2.1444x; 1.6744x over previous
#include <cuda_runtime.h>

#define CDIM 10000
#define CV4  2500
#define BDIM 4096
#define NT   256
#define NW   8
#define CAP  512
#define CUTF 1.80f
#define ITER4 10   // ceil(2500/256)

// dyn smem (floats): val 10000 | cand_logit 512 | cand_adj 512 | red 8 | wcnt 8
#define SMEM_BYTES ((CDIM + CAP + CAP + 8 + 8) * 4)

__device__ __align__(16) float g_partial[BDIM];
__device__ unsigned g_done = 0;

__device__ __forceinline__ unsigned key_of(float f) {
    unsigned u = __float_as_uint(f);
    return u ^ ((unsigned)((int)u >> 31) | 0x80000000u);
}
__device__ __forceinline__ float val_of(unsigned k) {
    unsigned m = ((int)k < 0) ? 0x80000000u : 0xFFFFFFFFu;
    return __uint_as_float(k ^ m);
}

// exp(x), pure FFMA (no MUFU), valid x <= ~1, rel err ~2e-7.
__device__ __forceinline__ float fexp_(float x) {
    x = fmaxf(x, -87.0f);
    const float LOG2E = 1.4426950408889634f;
    float t = fmaf(x, LOG2E, 12582912.0f);
    unsigned ei = __float_as_uint(t);
    float f = fmaf(x, LOG2E, -(t - 12582912.0f));
    float p = 1.3333558146e-3f;
    p = fmaf(p, f, 9.6181291076e-3f);
    p = fmaf(p, f, 5.5504108664e-2f);
    p = fmaf(p, f, 2.4022650695910071e-1f);
    p = fmaf(p, f, 6.9314718055994531e-1f);
    p = fmaf(p, f, 1.0f);
    return p * __uint_as_float((ei << 23) + 0x3F800000u);
}

__global__ void __launch_bounds__(NT, 5) row_kernel(
    const float* __restrict__ logit, const int* __restrict__ target,
    const float* __restrict__ lcn,   const int* __restrict__ kpc,
    float* __restrict__ out)
{
    extern __shared__ float smem[];
    float*    s_val  = smem;                 // [10000] raw logits
    float*    s_cl   = s_val + CDIM;         // [512] candidate logits
    float*    s_ca   = s_cl + CAP;           // [512] candidate adjusted
    float*    s_red  = s_ca + CAP;           // [8]
    unsigned* s_wcnt = (unsigned*)(s_red + 8); // [8]

    __shared__ float    s_Z, s_T;
    __shared__ int      s_k, s_tg, s_last;
    __shared__ unsigned s_n, s_cnt;

    const int row  = blockIdx.x;
    const int tid  = threadIdx.x;
    const int lane = tid & 31;
    const int wid  = tid >> 5;

    if (tid == NT - 1) {
        int tg = target[row];
        int k = kpc[tg];
        if (k > CDIM) k = CDIM;
        if (k < 1) k = 1;
        s_tg = tg; s_k = k;
    }

    // ---- pass 1: load row, store raw vals, Z = sum exp(logit+lcn), count >= CUTF ----
    const float4* l4 = (const float4*)(logit + (size_t)row * CDIM);
    const float4* w4 = (const float4*)lcn;

    float Z0 = 0.f, Z1 = 0.f;
    int cnt = 0;
    for (int j4 = tid; j4 < CV4; j4 += NT) {
        float4 L = __ldcs(l4 + j4);
        float4 W = __ldg(w4 + j4);
        ((float4*)s_val)[j4] = L;
        cnt += (L.x >= CUTF) + (L.y >= CUTF) + (L.z >= CUTF) + (L.w >= CUTF);
        Z0 += fexp_(L.x + W.x);
        Z1 += fexp_(L.y + W.y);
        Z0 += fexp_(L.z + W.z);
        Z1 += fexp_(L.w + W.w);
    }
    float Z = Z0 + Z1;
    #pragma unroll
    for (int o = 16; o; o >>= 1) {
        Z   += __shfl_xor_sync(0xFFFFFFFFu, Z, o);
        cnt += __shfl_xor_sync(0xFFFFFFFFu, cnt, o);
    }
    if (lane == 0) { s_red[wid] = Z; s_wcnt[wid] = (unsigned)cnt; }
    __syncthreads();

    if (tid == 0) {
        float Zt = 0.f;
        unsigned b = 0;
        #pragma unroll
        for (int w = 0; w < NW; w++) {
            Zt += s_red[w];
            unsigned c = s_wcnt[w];
            s_wcnt[w] = b;          // exclusive prefix -> warp base
            b += c;
        }
        s_Z = Zt; s_n = b; s_cnt = 0u;
    }
    __syncthreads();

    const unsigned n = s_n;
    const int k = s_k;
    const bool fast = ((int)n >= k && n <= CAP);

    if (fast) {
        // ---- deterministic ordered compaction: (logit, logit+lcn) pairs ----
        unsigned pos = s_wcnt[wid];
        for (int it = 0; it < ITER4; it++) {
            int j4 = wid * 32 + lane + it * NT;
            bool valid = (j4 < CV4);
            float4 L = valid ? ((const float4*)s_val)[j4]
                             : make_float4(-1e38f, -1e38f, -1e38f, -1e38f);
            float mx = fmaxf(fmaxf(L.x, L.y), fmaxf(L.z, L.w));
            if (__any_sync(0xFFFFFFFFu, mx >= CUTF)) {
                #pragma unroll
                for (int c = 0; c < 4; c++) {
                    float f = (c == 0) ? L.x : (c == 1) ? L.y : (c == 2) ? L.z : L.w;
                    bool sel = (f >= CUTF);
                    unsigned bal = __ballot_sync(0xFFFFFFFFu, sel);
                    if (sel) {
                        unsigned p = pos + __popc(bal & ((1u << lane) - 1u));
                        s_cl[p] = f;
                        s_ca[p] = f + __ldg(lcn + 4 * j4 + c);
                    }
                    pos += __popc(bal);
                }
            }
        }
        __syncthreads();

        // ---- warp-0 in-register bisection: exact k-th largest ----
        if (wid == 0) {
            float r[16];
            #pragma unroll
            for (int i = 0; i < 16; i++) {
                unsigned idx = lane + 32u * i;
                r[i] = (idx < n) ? s_cl[idx] : -1e38f;
            }
            float mx = r[0];
            #pragma unroll
            for (int i = 1; i < 16; i++) mx = fmaxf(mx, r[i]);
            #pragma unroll
            for (int o = 16; o; o >>= 1)
                mx = fmaxf(mx, __shfl_xor_sync(0xFFFFFFFFu, mx, o));
            unsigned lo = key_of(CUTF), hi = key_of(mx) + 1u;
            while (hi - lo > 1u) {
                unsigned mid = lo + ((hi - lo) >> 1);
                float mv = val_of(mid);
                int c = 0;
                #pragma unroll
                for (int i = 0; i < 16; i++) c += (r[i] >= mv);
                c = __reduce_add_sync(0xFFFFFFFFu, c);
                if (c >= k) lo = mid; else hi = mid;
            }
            if (lane == 0) s_T = val_of(lo);
        }
        __syncthreads();

        // ---- masked exp-sum over candidates (fixed order) ----
        const float T = s_T;
        float s = 0.f;
        for (unsigned i = tid; i < n; i += NT)
            if (s_cl[i] >= T) s += fexp_(s_ca[i]);
        #pragma unroll
        for (int o = 16; o; o >>= 1) s += __shfl_xor_sync(0xFFFFFFFFu, s, o);
        if (lane == 0) s_red[wid] = s;
        __syncthreads();
    } else {
        // ---- exact fallback: block bisection over full array ----
        unsigned lo = 0u, hi = 0xFFFFFFFFu;
        while (hi - lo > 1u) {
            unsigned mid = lo + ((hi - lo) >> 1);
            float mv = val_of(mid);
            unsigned c = 0;
            for (int j = tid; j < CDIM; j += NT) c += (s_val[j] >= mv);
            atomicAdd(&s_cnt, c);
            __syncthreads();
            unsigned ct = s_cnt;
            __syncthreads();
            if (tid == 0) s_cnt = 0u;
            if ((int)ct >= k) lo = mid; else hi = mid;
            __syncthreads();
        }
        if (tid == 0) s_T = val_of(lo);
        __syncthreads();
        const float T = s_T;
        float s = 0.f;
        for (int j = tid; j < CDIM; j += NT) {
            float f = s_val[j];
            if (f >= T) s += fexp_(f + __ldg(lcn + j));
        }
        #pragma unroll
        for (int o = 16; o; o >>= 1) s += __shfl_xor_sync(0xFFFFFFFFu, s, o);
        if (lane == 0) s_red[wid] = s;
        __syncthreads();
    }

    // ---- per-row loss, then last-CTA global reduction ----
    if (tid == 0) {
        float S = 0.f;
        #pragma unroll
        for (int w = 0; w < NW; w++) S += s_red[w];
        float Zt = s_Z;
        float T  = s_T;
        int   tg = s_tg;
        float ft = s_val[tg];
        float at = ft + __ldg(lcn + tg);
        float pt = (ft >= T) ? (fexp_(at) / Zt) : 0.f;
        float den = S / Zt + 0.01f;                // + 1e-6 * C
        float num = pt + 1e-6f;
        float part = 0.5f * (logf(Zt) - at) + 0.5f * (logf(den) - logf(num));
        g_partial[row] = part;
        __threadfence();
        unsigned t = atomicAdd(&g_done, 1u);
        s_last = (t == BDIM - 1u);
    }
    __syncthreads();

    if (s_last) {
        if (tid == 0) g_done = 0u;
        __threadfence();
        float acc = 0.f;
        #pragma unroll
        for (int i = 0; i < BDIM / 4 / NT; i++) {
            float4 v = ((const float4*)g_partial)[tid + i * NT];
            acc += (v.x + v.y) + (v.z + v.w);
        }
        #pragma unroll
        for (int o = 16; o; o >>= 1) acc += __shfl_xor_sync(0xFFFFFFFFu, acc, o);
        if (lane == 0) s_red[wid] = acc;
        __syncthreads();
        if (tid == 0) {
            float S = 0.f;
            #pragma unroll
            for (int w = 0; w < NW; w++) S += s_red[w];
            out[0] = S * (1.0f / BDIM);
        }
    }
}

extern "C" void kernel_launch(void* const* d_in, const int* in_sizes, int n_in,
                              void* d_out, int out_size) {
    const float* logit  = (const float*)d_in[0];
    const int*   target = (const int*)d_in[1];
    const float* lcn    = (const float*)d_in[2];
    const int*   kpc    = (const int*)d_in[3];
    float* out = (float*)d_out;

    cudaFuncSetAttribute(row_kernel,
                         cudaFuncAttributePreferredSharedMemoryCarveout,
                         cudaSharedmemCarveoutMaxShared);
    row_kernel<<<BDIM, NT, SMEM_BYTES>>>(logit, target, lcn, kpc, out);
}

// round 13
// speedup vs baseline: 2.6641x; 1.2423x over previous
#include <cuda_runtime.h>

#define CDIM 10000
#define CV4  2500
#define CV4PAD 2560   // 10 full iterations of 256 -> no partial-warp collectives
#define BDIM 4096
#define NT   256
#define NW   8
#define WCAP 64      // staging slots per warp
#define DCAP 384     // dense candidate cap (12 regs/lane in warp-0 bisection)
#define CUTF 2.0f

__device__ __align__(16) float g_partial[BDIM];
__device__ unsigned g_done = 0;

__device__ __forceinline__ unsigned key_of(float f) {
    unsigned u = __float_as_uint(f);
    return u ^ ((unsigned)((int)u >> 31) | 0x80000000u);
}
__device__ __forceinline__ float val_of(unsigned k) {
    unsigned m = ((int)k < 0) ? 0x80000000u : 0xFFFFFFFFu;
    return __uint_as_float(k ^ m);
}

// exp(x), pure FFMA, deg-4, valid for |x| < ~80, rel err ~3e-5.
__device__ __forceinline__ float fexp_(float x) {
    const float LOG2E = 1.4426950408889634f;
    float t = fmaf(x, LOG2E, 12582912.0f);        // 1.5*2^23 rounding magic
    float f = fmaf(x, LOG2E, -(t - 12582912.0f)); // f in [-0.5, 0.5]
    float p =          9.6181291076e-3f;
    p = fmaf(p, f, 5.5504108664e-2f);
    p = fmaf(p, f, 2.4022650695910071e-1f);
    p = fmaf(p, f, 6.9314718055994531e-1f);
    p = fmaf(p, f, 1.0f);
    return p * __uint_as_float((__float_as_uint(t) << 23) + 0x3F800000u);
}

__global__ void __launch_bounds__(NT, 6) row_kernel(
    const float* __restrict__ logit, const int* __restrict__ target,
    const float* __restrict__ lcn,   const int* __restrict__ kpc,
    float* __restrict__ out)
{
    __shared__ float    s_sv[NW * WCAP];   // staged candidate logits (per-warp regions)
    __shared__ float    s_sa[NW * WCAP];   // staged candidate adjusted
    __shared__ float    s_dv[DCAP];        // dense candidate logits
    __shared__ float    s_da[DCAP];        // dense candidate adjusted
    __shared__ float    s_red[NW];
    __shared__ unsigned s_wcnt[NW], s_base[NW];
    __shared__ float    s_Z, s_T, s_ft, s_at;
    __shared__ int      s_k, s_last, s_fast;
    __shared__ unsigned s_n, s_cnt;

    const int row  = blockIdx.x;
    const int tid  = threadIdx.x;
    const int lane = tid & 31;
    const int wid  = tid >> 5;
    const unsigned lmask = (1u << lane) - 1u;

    const float* lrow = logit + (size_t)row * CDIM;

    // early dependent loads (overlap with pass 1 via other warps)
    if (tid == NT - 1) {
        int tg = __ldg(target + row);
        int k  = __ldg(kpc + tg);
        if (k > CDIM) k = CDIM;
        if (k < 1) k = 1;
        float ft = __ldg(lrow + tg);
        s_k = k; s_ft = ft; s_at = ft + __ldg(lcn + tg);
    }

    // ---- pass 1: stream row, Z = sum exp(l+w), fused ordered candidate staging ----
    // PADDED to CV4PAD so every warp executes every iteration with all 32 lanes
    // (full-mask ballots below are only safe with complete warps).
    const float4* l4 = (const float4*)lrow;
    const float4* w4 = (const float4*)lcn;

    float Z0 = 0.f, Z1 = 0.f;
    unsigned pos = wid * WCAP;
    const unsigned lim = wid * WCAP + WCAP;
    for (int j4 = tid; j4 < CV4PAD; j4 += NT) {
        const bool valid = (j4 < CV4);
        float4 L, W;
        if (valid) { L = __ldcs(l4 + j4); W = __ldg(w4 + j4); }
        else {
            L = make_float4(-40.f, -40.f, -40.f, -40.f);  // fexp ~ 4e-18, never selected
            W = make_float4(0.f, 0.f, 0.f, 0.f);
        }
        Z0 += fexp_(L.x + W.x);
        Z1 += fexp_(L.y + W.y);
        Z0 += fexp_(L.z + W.z);
        Z1 += fexp_(L.w + W.w);
        #pragma unroll
        for (int c = 0; c < 4; c++) {
            float f = (c == 0) ? L.x : (c == 1) ? L.y : (c == 2) ? L.z : L.w;
            bool sel = (f >= CUTF);
            unsigned bal = __ballot_sync(0xFFFFFFFFu, sel);
            if (sel) {
                unsigned p = pos + __popc(bal & lmask);
                if (p < lim) {
                    float w = (c == 0) ? W.x : (c == 1) ? W.y : (c == 2) ? W.z : W.w;
                    s_sv[p] = f;
                    s_sa[p] = f + w;
                }
            }
            pos += __popc(bal);
        }
    }
    float Z = Z0 + Z1;
    #pragma unroll
    for (int o = 16; o; o >>= 1) Z += __shfl_xor_sync(0xFFFFFFFFu, Z, o);
    if (lane == 0) { s_red[wid] = Z; s_wcnt[wid] = pos - wid * WCAP; }
    __syncthreads();

    if (tid == 0) {
        float Zt = 0.f;
        unsigned b = 0, mx = 0;
        #pragma unroll
        for (int w = 0; w < NW; w++) {
            Zt += s_red[w];
            unsigned c = s_wcnt[w];
            mx = max(mx, c);
            s_base[w] = b;
            b += c;
        }
        s_Z = Zt; s_n = b; s_cnt = 0u;
        s_fast = ((int)b >= s_k) && (b <= DCAP) && (mx <= WCAP);
    }
    __syncthreads();

    const unsigned n = s_n;
    const int k = s_k;

    if (s_fast) {
        // ---- dense copy (per-warp regions are contiguous) ----
        {
            unsigned cw = s_wcnt[wid], b = s_base[wid], src = wid * WCAP;
            for (unsigned i = lane; i < cw; i += 32) {
                s_dv[b + i] = s_sv[src + i];
                s_da[b + i] = s_sa[src + i];
            }
        }
        __syncthreads();

        // ---- warp-0 in-register bisection: exact k-th largest ----
        if (wid == 0) {
            float r[DCAP / 32];
            #pragma unroll
            for (int i = 0; i < DCAP / 32; i++) {
                unsigned idx = lane + 32u * i;
                r[i] = (idx < n) ? s_dv[idx] : -1e38f;
            }
            float mx = r[0];
            #pragma unroll
            for (int i = 1; i < DCAP / 32; i++) mx = fmaxf(mx, r[i]);
            #pragma unroll
            for (int o = 16; o; o >>= 1)
                mx = fmaxf(mx, __shfl_xor_sync(0xFFFFFFFFu, mx, o));
            unsigned lo = key_of(CUTF), hi = key_of(mx) + 1u;
            while (hi - lo > 1u) {
                unsigned mid = lo + ((hi - lo) >> 1);
                float mv = val_of(mid);
                int c = 0;
                #pragma unroll
                for (int i = 0; i < DCAP / 32; i++) c += (r[i] >= mv);
                c = __reduce_add_sync(0xFFFFFFFFu, c);
                if (c >= k) lo = mid; else hi = mid;
            }
            if (lane == 0) s_T = val_of(lo);
        }
        __syncthreads();

        // ---- masked exp-sum over dense candidates (fixed order) ----
        const float T = s_T;
        float s = 0.f;
        for (unsigned i = tid; i < n; i += NT)
            if (s_dv[i] >= T) s += fexp_(s_da[i]);
        #pragma unroll
        for (int o = 16; o; o >>= 1) s += __shfl_xor_sync(0xFFFFFFFFu, s, o);
        if (lane == 0) s_red[wid] = s;
        __syncthreads();
    } else {
        // ---- exact fallback: block bisection over gmem row (near-unreachable) ----
        unsigned lo = 0u, hi = 0xFFFFFFFFu;
        while (hi - lo > 1u) {
            unsigned mid = lo + ((hi - lo) >> 1);
            float mv = val_of(mid);
            unsigned c = 0;
            for (int j = tid; j < CDIM; j += NT) c += (__ldg(lrow + j) >= mv);
            atomicAdd(&s_cnt, c);
            __syncthreads();
            unsigned ct = s_cnt;
            __syncthreads();
            if (tid == 0) s_cnt = 0u;
            if ((int)ct >= k) lo = mid; else hi = mid;
            __syncthreads();
        }
        if (tid == 0) s_T = val_of(lo);
        __syncthreads();
        const float T = s_T;
        float s = 0.f;
        for (int j = tid; j < CDIM; j += NT) {
            float f = __ldg(lrow + j);
            if (f >= T) s += fexp_(f + __ldg(lcn + j));
        }
        #pragma unroll
        for (int o = 16; o; o >>= 1) s += __shfl_xor_sync(0xFFFFFFFFu, s, o);
        if (lane == 0) s_red[wid] = s;
        __syncthreads();
    }

    // ---- per-row loss, then last-CTA global reduction ----
    if (tid == 0) {
        float S = 0.f;
        #pragma unroll
        for (int w = 0; w < NW; w++) S += s_red[w];
        float Zt = s_Z;
        float T  = s_T;
        float ft = s_ft;
        float at = s_at;
        float pt = (ft >= T) ? (fexp_(at) / Zt) : 0.f;
        float den = S / Zt + 0.01f;                // + 1e-6 * C
        float num = pt + 1e-6f;
        float part = 0.5f * (logf(Zt) - at) + 0.5f * (logf(den) - logf(num));
        g_partial[row] = part;
        __threadfence();
        unsigned t = atomicAdd(&g_done, 1u);
        s_last = (t == BDIM - 1u);
    }
    __syncthreads();

    if (s_last) {
        if (tid == 0) g_done = 0u;
        __threadfence();
        float acc = 0.f;
        #pragma unroll
        for (int i = 0; i < BDIM / 4 / NT; i++) {
            float4 v = ((const float4*)g_partial)[tid + i * NT];
            acc += (v.x + v.y) + (v.z + v.w);
        }
        #pragma unroll
        for (int o = 16; o; o >>= 1) acc += __shfl_xor_sync(0xFFFFFFFFu, acc, o);
        if (lane == 0) s_red[wid] = acc;
        __syncthreads();
        if (tid == 0) {
            float S = 0.f;
            #pragma unroll
            for (int w = 0; w < NW; w++) S += s_red[w];
            out[0] = S * (1.0f / BDIM);
        }
    }
}

extern "C" void kernel_launch(void* const* d_in, const int* in_sizes, int n_in,
                              void* d_out, int out_size) {
    const float* logit  = (const float*)d_in[0];
    const int*   target = (const int*)d_in[1];
    const float* lcn    = (const float*)d_in[2];
    const int*   kpc    = (const int*)d_in[3];
    float* out = (float*)d_out;

    row_kernel<<<BDIM, NT>>>(logit, target, lcn, kpc, out);
}